// round 2
// baseline (speedup 1.0000x reference)
#include <cuda_runtime.h>
#include <cstdint>

#define NROWS 8192
#define D 128
#define ALPHA 2.0f
#define SHIFT 40.0f

typedef unsigned long long ull;

// Scratch (no allocations allowed): partial exp-sums per j-chunk, diag, pt partials.
__device__ float g_pos_part[16][NROWS];
__device__ float g_neg_part[16][NROWS];
__device__ float g_at_diag[NROWS];
__device__ float g_pt_part[64];

// Packed fp32x2 FMA (sm_103a): 2 MACs per fma-pipe slot.
#define FFMA2(acc, a, b) \
    asm("fma.rn.f32x2 %0, %1, %2, %0;" : "+l"(acc) : "l"(a), "l"(b))
#define PACK_DUP(out, x) \
    asm("mov.b64 %0, {%1, %1};" : "=l"(out) : "f"(x))
#define UNPACK2(lo, hi, v) \
    asm("mov.b64 {%0, %1}, %2;" : "=f"(lo), "=f"(hi) : "l"(v))

// Shared memory layout (floats)
#define A_STRIDE 132   // 128 + 4 pad, keeps float4 alignment, A loads are broadcast
#define BT_STRIDE 66   // B stored transposed [k][col], pad for bank spread
#define SM_ATP_OFF (128 * A_STRIDE)
#define SM_BAU_OFF (2 * 128 * A_STRIDE)
#define SM_BTP_OFF (2 * 128 * A_STRIDE + 128 * BT_STRIDE)
#define SM_TOTAL_FLOATS (2 * 128 * A_STRIDE + 2 * 128 * BT_STRIDE)  // 50688 -> 202752 B

// Main fused kernel: each CTA computes a 128-row x 512-col region of all three
// similarity matrices (8 tiles of 128x64), folding each tile into per-row
// shifted exp-sums.  grid = (64 i-tiles, 16 j-chunks).
__global__ __launch_bounds__(256, 1)
void supcon_main(const float* __restrict__ zau, const float* __restrict__ ztp) {
    extern __shared__ float smem[];
    float* sAau = smem;
    float* sAtp = smem + SM_ATP_OFF;
    float* sBau = smem + SM_BAU_OFF;
    float* sBtp = smem + SM_BTP_OFF;

    const int tid = threadIdx.x;
    const int tx = tid & 15;      // 16 col-groups
    const int ty = tid >> 4;      // 16 row-groups
    const int r0 = ty * 8;        // 8 rows per thread
    const int c0 = tx * 4;        // 4 cols per thread (2 packed pairs)
    const int ibase = blockIdx.x * 128;

    // Load A tiles (i-rows), row-major.
#pragma unroll
    for (int u = 0; u < 16; ++u) {
        int e = tid + u * 256;          // 0..4095
        int row = e >> 5, k4 = e & 31;
        float4 va = *(const float4*)&zau[(size_t)(ibase + row) * D + k4 * 4];
        float4 vt = *(const float4*)&ztp[(size_t)(ibase + row) * D + k4 * 4];
        *(float4*)&sAau[row * A_STRIDE + k4 * 4] = va;
        *(float4*)&sAtp[row * A_STRIDE + k4 * 4] = vt;
    }

    float pos_s[8], neg_s[8];
#pragma unroll
    for (int r = 0; r < 8; ++r) { pos_s[r] = 0.f; neg_s[r] = 0.f; }

    for (int t = 0; t < 8; ++t) {
        const int jbase = (blockIdx.y * 8 + t) * 64;
        __syncthreads();
        // Load B tile (j-rows) transposed to [k][col] so adjacent cols form f32x2 pairs.
#pragma unroll
        for (int u = 0; u < 8; ++u) {
            int e = tid + u * 256;      // 0..2047
            int row = e >> 5, k4 = e & 31;
            float4 va = *(const float4*)&zau[(size_t)(jbase + row) * D + k4 * 4];
            float4 vt = *(const float4*)&ztp[(size_t)(jbase + row) * D + k4 * 4];
            float* pa = &sBau[(k4 * 4) * BT_STRIDE + row];
            pa[0] = va.x; pa[BT_STRIDE] = va.y; pa[2 * BT_STRIDE] = va.z; pa[3 * BT_STRIDE] = va.w;
            float* pt = &sBtp[(k4 * 4) * BT_STRIDE + row];
            pt[0] = vt.x; pt[BT_STRIDE] = vt.y; pt[2 * BT_STRIDE] = vt.z; pt[3 * BT_STRIDE] = vt.w;
        }
        __syncthreads();

        ull acc_aa[8][2], acc_tt[8][2], acc_at[8][2];
#pragma unroll
        for (int r = 0; r < 8; ++r) {
#pragma unroll
            for (int p = 0; p < 2; ++p) {
                acc_aa[r][p] = 0ull; acc_tt[r][p] = 0ull; acc_at[r][p] = 0ull;
            }
        }

#pragma unroll 4
        for (int k2 = 0; k2 < 64; ++k2) {
            float2 aau[8], atp[8];
#pragma unroll
            for (int r = 0; r < 8; ++r) {
                aau[r] = *(const float2*)&sAau[(r0 + r) * A_STRIDE + k2 * 2];
                atp[r] = *(const float2*)&sAtp[(r0 + r) * A_STRIDE + k2 * 2];
            }
#pragma unroll
            for (int kk = 0; kk < 2; ++kk) {
                const int k = k2 * 2 + kk;
                const ull bau0 = *(const ull*)&sBau[k * BT_STRIDE + c0];
                const ull bau1 = *(const ull*)&sBau[k * BT_STRIDE + c0 + 2];
                const ull btp0 = *(const ull*)&sBtp[k * BT_STRIDE + c0];
                const ull btp1 = *(const ull*)&sBtp[k * BT_STRIDE + c0 + 2];
#pragma unroll
                for (int r = 0; r < 8; ++r) {
                    float a = kk ? aau[r].y : aau[r].x;
                    float b = kk ? atp[r].y : atp[r].x;
                    ull a2, b2;
                    PACK_DUP(a2, a);
                    PACK_DUP(b2, b);
                    FFMA2(acc_aa[r][0], a2, bau0); FFMA2(acc_aa[r][1], a2, bau1);
                    FFMA2(acc_tt[r][0], b2, btp0); FFMA2(acc_tt[r][1], b2, btp1);
                    FFMA2(acc_at[r][0], a2, btp0); FFMA2(acc_at[r][1], a2, btp1);
                }
            }
        }

        // Fold tile into shifted exp-sums; capture alpha-diagonal.
#pragma unroll
        for (int r = 0; r < 8; ++r) {
            const int gi = ibase + r0 + r;
#pragma unroll
            for (int p = 0; p < 2; ++p) {
                float aa0, aa1, tt0, tt1, at0, at1;
                UNPACK2(aa0, aa1, acc_aa[r][p]);
                UNPACK2(tt0, tt1, acc_tt[r][p]);
                UNPACK2(at0, at1, acc_at[r][p]);
                const int gj = jbase + c0 + 2 * p;
                if (gi != gj) {
                    pos_s[r] += __expf(aa0 - SHIFT) + __expf(tt0 - SHIFT);
                    neg_s[r] += __expf(at0 - SHIFT);
                } else {
                    g_at_diag[gi] = at0;
                }
                if (gi != gj + 1) {
                    pos_s[r] += __expf(aa1 - SHIFT) + __expf(tt1 - SHIFT);
                    neg_s[r] += __expf(at1 - SHIFT);
                } else {
                    g_at_diag[gi] = at1;
                }
            }
        }
    }

    // Deterministic cross-tx reduction (reuse B region).
    __syncthreads();
    float* red_pos = sBau;               // 128*16 floats
    float* red_neg = sBau + 128 * 16;
#pragma unroll
    for (int r = 0; r < 8; ++r) {
        red_pos[(r0 + r) * 16 + tx] = pos_s[r];
        red_neg[(r0 + r) * 16 + tx] = neg_s[r];
    }
    __syncthreads();
    if (tid < 128) {
        float ps = 0.f, ns = 0.f;
#pragma unroll
        for (int u = 0; u < 16; ++u) {
            ps += red_pos[tid * 16 + u];
            ns += red_neg[tid * 16 + u];
        }
        g_pos_part[blockIdx.y][ibase + tid] = ps;
        g_neg_part[blockIdx.y][ibase + tid] = ns;
    }
}

// pt_loss partials: sum over rows of (au - tp) . (pt1 - pt0)
__global__ void pt_kernel(const float* __restrict__ zau, const float* __restrict__ ztp,
                          const float* __restrict__ fc) {
    __shared__ float w[D];
    __shared__ float red[256];
    const int tid = threadIdx.x;
    if (tid < D) w[tid] = fc[D + tid] - fc[tid];
    __syncthreads();
    float s = 0.f;
    const size_t base = (size_t)blockIdx.x * 16384;
    for (int e = tid; e < 16384; e += 256)
        s += (zau[base + e] - ztp[base + e]) * w[e & (D - 1)];
    red[tid] = s;
    __syncthreads();
    for (int off = 128; off > 0; off >>= 1) {
        if (tid < off) red[tid] += red[tid + off];
        __syncthreads();
    }
    if (tid == 0) g_pt_part[blockIdx.x] = red[0];
}

// Final combine: shift cancels in log(neg)-log(pos); fp64 accumulation.
__global__ void final_kernel(float* __restrict__ out) {
    __shared__ double red[256];
    const int tid = threadIdx.x;
    double s = 0.0;
    for (int i = tid; i < NROWS; i += 256) {
        float ps = 0.f, ns = 0.f;
#pragma unroll
        for (int c = 0; c < 16; ++c) {
            ps += g_pos_part[c][i];
            ns += g_neg_part[c][i];
        }
        s += (double)(logf(ns) - logf(ps) + ALPHA * g_at_diag[i]);
    }
    red[tid] = s;
    __syncthreads();
    for (int off = 128; off > 0; off >>= 1) {
        if (tid < off) red[tid] += red[tid + off];
        __syncthreads();
    }
    if (tid == 0) {
        double pt = 0.0;
        for (int b = 0; b < 64; ++b) pt += (double)g_pt_part[b];
        pt /= (double)NROWS;
        out[0] = (float)((pt + red[0]) / (double)(NROWS + 2));
    }
}

extern "C" void kernel_launch(void* const* d_in, const int* in_sizes, int n_in,
                              void* d_out, int out_size) {
    const float* zau = (const float*)d_in[0];   // [8192,128] f32
    const float* ztp = (const float*)d_in[1];   // [8192,128] f32
    const float* fc  = (const float*)d_in[2];   // [2,128] f32
    // d_in[3]: labels (int64) — unused by the math.
    float* out = (float*)d_out;

    const size_t smem_bytes = (size_t)SM_TOTAL_FLOATS * sizeof(float);  // 202752
    cudaFuncSetAttribute(supcon_main, cudaFuncAttributeMaxDynamicSharedMemorySize,
                         (int)smem_bytes);

    dim3 grid(64, 16);
    supcon_main<<<grid, 256, smem_bytes>>>(zau, ztp);
    pt_kernel<<<64, 256>>>(zau, ztp, fc);
    final_kernel<<<1, 256>>>(out);
}

// round 6
// speedup vs baseline: 2.2140x; 2.2140x over previous
#include <cuda_runtime.h>
#include <cuda_bf16.h>
#include <cstdint>

#define NROWS 8192
#define DIM 128
#define ALPHA 2.0f
#define SHIFT 40.0f
#define BM 128
#define BN 64
#define JCHUNKS 16
#define TILES 8              // j-tiles per chunk: 8192/16/64

__device__ float g_pos_part[JCHUNKS][NROWS];
__device__ float g_neg_part[JCHUNKS][NROWS];
__device__ float g_at_diag[NROWS];
__device__ float g_pt_part[64];

// ---------------- smem layout (bytes), bf16 tiles, row stride 136 elems (272B)
#define ASTRIDE 136
#define SM_A_AU_HI 0
#define SM_A_AU_LO 34816
#define SM_A_TP_HI 69632
#define SM_A_TP_LO 104448
#define SM_B_AU_HI 139264
#define SM_B_AU_LO 156672
#define SM_B_TP_HI 174080
#define SM_B_TP_LO 191488
#define SM_TOTAL   208896

__device__ __forceinline__ uint32_t smem_u32(const void* p) {
    uint32_t a;
    asm("{ .reg .u64 t; cvta.to.shared.u64 t, %1; cvt.u32.u64 %0, t; }" : "=r"(a) : "l"(p));
    return a;
}

#define LDSM4(r0, r1, r2, r3, addr)                                             \
    asm volatile("ldmatrix.sync.aligned.m8n8.x4.shared.b16 {%0,%1,%2,%3}, [%4];" \
                 : "=r"(r0), "=r"(r1), "=r"(r2), "=r"(r3) : "r"(addr))

#define MMA16816(d, a, b0r, b1r)                                                \
    asm volatile("mma.sync.aligned.m16n8k16.row.col.f32.bf16.bf16.f32 "         \
                 "{%0,%1,%2,%3}, {%4,%5,%6,%7}, {%8,%9}, {%0,%1,%2,%3};"        \
                 : "+f"((d)[0]), "+f"((d)[1]), "+f"((d)[2]), "+f"((d)[3])       \
                 : "r"((a)[0]), "r"((a)[1]), "r"((a)[2]), "r"((a)[3]),          \
                   "r"(b0r), "r"(b1r))

// fp32 rows -> bf16 hi/lo tiles (row-major, stride ASTRIDE). n_f4 = rows*32.
__device__ __forceinline__ void load_operand(const float* __restrict__ src,
                                             char* hi, char* lo,
                                             int n_f4, int t, int nt) {
    for (int e = t; e < n_f4; e += nt) {
        int row = e >> 5;
        int c4  = (e & 31) << 2;
        float4 v = *(const float4*)(src + (size_t)row * DIM + c4);
        __nv_bfloat162 h01 = __floats2bfloat162_rn(v.x, v.y);
        __nv_bfloat162 h23 = __floats2bfloat162_rn(v.z, v.w);
        float2 f01 = __bfloat1622float2(h01);
        float2 f23 = __bfloat1622float2(h23);
        __nv_bfloat162 l01 = __floats2bfloat162_rn(v.x - f01.x, v.y - f01.y);
        __nv_bfloat162 l23 = __floats2bfloat162_rn(v.z - f23.x, v.w - f23.y);
        uint32_t off = (uint32_t)(row * ASTRIDE + c4) * 2u;
        *(uint2*)(hi + off) = make_uint2(*(uint32_t*)&h01, *(uint32_t*)&h23);
        *(uint2*)(lo + off) = make_uint2(*(uint32_t*)&l01, *(uint32_t*)&l23);
    }
}

__global__ __launch_bounds__(256, 1)
void supcon_hmma(const float* __restrict__ zau, const float* __restrict__ ztp) {
    extern __shared__ char smem[];
    const uint32_t sb = smem_u32(smem);
    const int tid = threadIdx.x;
    const int wid = tid >> 5, lane = tid & 31;
    const int wm = wid & 3, wn = wid >> 2;          // warp grid 4(M) x 2(N)
    const int m0 = wm * 32, n0 = wn * 32;
    const int g = lane >> 2, t4 = lane & 3;
    const int ibase = blockIdx.x * BM;
    const int jcbase = blockIdx.y * (NROWS / JCHUNKS);

    // Prologue: A tiles (resident for whole CTA) + B tile 0
    load_operand(zau + (size_t)ibase * DIM, smem + SM_A_AU_HI, smem + SM_A_AU_LO, BM * 32, tid, 256);
    load_operand(ztp + (size_t)ibase * DIM, smem + SM_A_TP_HI, smem + SM_A_TP_LO, BM * 32, tid, 256);
    load_operand(zau + (size_t)jcbase * DIM, smem + SM_B_AU_HI, smem + SM_B_AU_LO, BN * 32, tid, 256);
    load_operand(ztp + (size_t)jcbase * DIM, smem + SM_B_TP_HI, smem + SM_B_TP_LO, BN * 32, tid, 256);

    // ldmatrix per-lane addresses.
    // A matrices order: (m,k),(m+8,k),(m,k+8),(m+8,k+8)
    const int rowA = (((lane >> 3) & 1) << 3) + (lane & 7);
    const int colA = ((lane >> 4) & 1) << 3;
    // B matrices order: (n,k),(n,k+8),(n+8,k),(n+8,k+8)
    const int rowB = (((lane >> 4) & 1) << 3) + (lane & 7);
    const int colB = ((lane >> 3) & 1) << 3;

    uint32_t aAddr[4], bAddr[4];
    {
        const uint32_t aoff = (uint32_t)((m0 + rowA) * ASTRIDE + colA) * 2u;
        const uint32_t boff = (uint32_t)((n0 + rowB) * ASTRIDE + colB) * 2u;
        aAddr[0] = sb + SM_A_AU_HI + aoff;  aAddr[1] = sb + SM_A_AU_LO + aoff;
        aAddr[2] = sb + SM_A_TP_HI + aoff;  aAddr[3] = sb + SM_A_TP_LO + aoff;
        bAddr[0] = sb + SM_B_AU_HI + boff;  bAddr[1] = sb + SM_B_AU_LO + boff;
        bAddr[2] = sb + SM_B_TP_HI + boff;  bAddr[3] = sb + SM_B_TP_LO + boff;
    }
    const uint32_t MSTEP = 16u * ASTRIDE * 2u;   // +16 rows

    const int row_base = ibase + m0 + g;
    float pos_loc[4] = {0.f, 0.f, 0.f, 0.f};
    float neg_loc[4] = {0.f, 0.f, 0.f, 0.f};

    __syncthreads();

    for (int t = 0; t < TILES; ++t) {
        const int jb = jcbase + t * BN;

        float acc[3][2][4][4];
#pragma unroll
        for (int mt = 0; mt < 3; ++mt)
#pragma unroll
            for (int m = 0; m < 2; ++m)
#pragma unroll
                for (int n = 0; n < 4; ++n)
#pragma unroll
                    for (int d = 0; d < 4; ++d)
                        acc[mt][m][n][d] = 0.f;

        uint32_t koff = 0;
        for (int ks = 0; ks < 8; ++ks, koff += 32) {
            uint32_t aF[4][2][4];
            uint32_t bF[4][4][2];
#pragma unroll
            for (int v = 0; v < 4; ++v) {
                LDSM4(aF[v][0][0], aF[v][0][1], aF[v][0][2], aF[v][0][3], aAddr[v] + koff);
                LDSM4(aF[v][1][0], aF[v][1][1], aF[v][1][2], aF[v][1][3], aAddr[v] + MSTEP + koff);
                LDSM4(bF[v][0][0], bF[v][0][1], bF[v][1][0], bF[v][1][1], bAddr[v] + koff);
                LDSM4(bF[v][2][0], bF[v][2][1], bF[v][3][0], bF[v][3][1], bAddr[v] + MSTEP + koff);
            }
#pragma unroll
            for (int m = 0; m < 2; ++m) {
#pragma unroll
                for (int n = 0; n < 4; ++n) {
                    // aa = auh*auh + auh*aul + aul*auh
                    MMA16816(acc[0][m][n], aF[0][m], bF[0][n][0], bF[0][n][1]);
                    MMA16816(acc[0][m][n], aF[0][m], bF[1][n][0], bF[1][n][1]);
                    MMA16816(acc[0][m][n], aF[1][m], bF[0][n][0], bF[0][n][1]);
                    // tt
                    MMA16816(acc[1][m][n], aF[2][m], bF[2][n][0], bF[2][n][1]);
                    MMA16816(acc[1][m][n], aF[2][m], bF[3][n][0], bF[3][n][1]);
                    MMA16816(acc[1][m][n], aF[3][m], bF[2][n][0], bF[2][n][1]);
                    // at
                    MMA16816(acc[2][m][n], aF[0][m], bF[2][n][0], bF[2][n][1]);
                    MMA16816(acc[2][m][n], aF[0][m], bF[3][n][0], bF[3][n][1]);
                    MMA16816(acc[2][m][n], aF[1][m], bF[2][n][0], bF[2][n][1]);
                }
            }
        }

        // In-register epilogue: exp-sums with diagonal exclusion.
        const int col_base = jb + n0 + 2 * t4;
#pragma unroll
        for (int m = 0; m < 2; ++m) {
#pragma unroll
            for (int n = 0; n < 4; ++n) {
#pragma unroll
                for (int d = 0; d < 4; ++d) {
                    const int gi = row_base + m * 16 + ((d >> 1) << 3);
                    const int gj = col_base + n * 8 + (d & 1);
                    float e1 = __expf(acc[0][m][n][d] - SHIFT) +
                               __expf(acc[1][m][n][d] - SHIFT);
                    float e2 = __expf(acc[2][m][n][d] - SHIFT);
                    if (gi != gj) {
                        pos_loc[m * 2 + (d >> 1)] += e1;
                        neg_loc[m * 2 + (d >> 1)] += e2;
                    }
                }
            }
        }

        __syncthreads();              // done reading B tile t
        if (t + 1 < TILES) {
            const int jn = jcbase + (t + 1) * BN;
            load_operand(zau + (size_t)jn * DIM, smem + SM_B_AU_HI, smem + SM_B_AU_LO, BN * 32, tid, 256);
            load_operand(ztp + (size_t)jn * DIM, smem + SM_B_TP_HI, smem + SM_B_TP_LO, BN * 32, tid, 256);
        }
        __syncthreads();              // B tile t+1 ready / smem reuse safe
    }

    // Reduce across t4 lanes (cols within frag), then across wn via smem.
#pragma unroll
    for (int i = 0; i < 4; ++i) {
        pos_loc[i] += __shfl_xor_sync(0xffffffff, pos_loc[i], 1);
        pos_loc[i] += __shfl_xor_sync(0xffffffff, pos_loc[i], 2);
        neg_loc[i] += __shfl_xor_sync(0xffffffff, neg_loc[i], 1);
        neg_loc[i] += __shfl_xor_sync(0xffffffff, neg_loc[i], 2);
    }
    float* rf = (float*)smem;     // [0:256) pos[row][wn], [256:512) neg[row][wn]
    if (t4 == 0) {
#pragma unroll
        for (int i = 0; i < 4; ++i) {
            const int m = i >> 1, h = i & 1;
            const int row = m0 + m * 16 + h * 8 + g;
            rf[row * 2 + wn] = pos_loc[i];
            rf[256 + row * 2 + wn] = neg_loc[i];
        }
    }
    __syncthreads();
    if (tid < 128) {
        g_pos_part[blockIdx.y][ibase + tid] = rf[tid * 2] + rf[tid * 2 + 1];
        g_neg_part[blockIdx.y][ibase + tid] = rf[256 + tid * 2] + rf[256 + tid * 2 + 1];
    }
}

// Exact fp32 diagonal: g_at_diag[i] = dot(au_i, tp_i)
__global__ void diag_kernel(const float* __restrict__ zau, const float* __restrict__ ztp) {
    const int row = blockIdx.x * 8 + (threadIdx.x >> 5);
    const int lid = threadIdx.x & 31;
    float4 a = *(const float4*)(zau + (size_t)row * DIM + lid * 4);
    float4 b = *(const float4*)(ztp + (size_t)row * DIM + lid * 4);
    float s = a.x * b.x + a.y * b.y + a.z * b.z + a.w * b.w;
#pragma unroll
    for (int off = 16; off > 0; off >>= 1)
        s += __shfl_xor_sync(0xffffffff, s, off);
    if (lid == 0) g_at_diag[row] = s;
}

// pt_loss partials: sum over rows of (au - tp) . (pt1 - pt0)
__global__ void pt_kernel(const float* __restrict__ zau, const float* __restrict__ ztp,
                          const float* __restrict__ fc) {
    __shared__ float w[DIM];
    __shared__ float red[256];
    const int tid = threadIdx.x;
    if (tid < DIM) w[tid] = fc[DIM + tid] - fc[tid];
    __syncthreads();
    float s = 0.f;
    const size_t base = (size_t)blockIdx.x * 16384;
    for (int e = tid; e < 16384; e += 256)
        s += (zau[base + e] - ztp[base + e]) * w[e & (DIM - 1)];
    red[tid] = s;
    __syncthreads();
    for (int off = 128; off > 0; off >>= 1) {
        if (tid < off) red[tid] += red[tid + off];
        __syncthreads();
    }
    if (tid == 0) g_pt_part[blockIdx.x] = red[0];
}

// Final combine: shift cancels in log(neg)-log(pos); fp64 accumulation.
__global__ void final_kernel(float* __restrict__ out) {
    __shared__ double red[256];
    const int tid = threadIdx.x;
    double s = 0.0;
    for (int i = tid; i < NROWS; i += 256) {
        float ps = 0.f, ns = 0.f;
#pragma unroll
        for (int c = 0; c < JCHUNKS; ++c) {
            ps += g_pos_part[c][i];
            ns += g_neg_part[c][i];
        }
        s += (double)(logf(ns) - logf(ps) + ALPHA * g_at_diag[i]);
    }
    red[tid] = s;
    __syncthreads();
    for (int off = 128; off > 0; off >>= 1) {
        if (tid < off) red[tid] += red[tid + off];
        __syncthreads();
    }
    if (tid == 0) {
        double pt = 0.0;
        for (int b = 0; b < 64; ++b) pt += (double)g_pt_part[b];
        pt /= (double)NROWS;
        out[0] = (float)((pt + red[0]) / (double)(NROWS + 2));
    }
}

extern "C" void kernel_launch(void* const* d_in, const int* in_sizes, int n_in,
                              void* d_out, int out_size) {
    const float* zau = (const float*)d_in[0];   // [8192,128] f32
    const float* ztp = (const float*)d_in[1];   // [8192,128] f32
    const float* fc  = (const float*)d_in[2];   // [2,128] f32
    // d_in[3]: labels (int64) — unused by the math.
    float* out = (float*)d_out;

    cudaFuncSetAttribute(supcon_hmma, cudaFuncAttributeMaxDynamicSharedMemorySize, SM_TOTAL);

    diag_kernel<<<1024, 256>>>(zau, ztp);
    dim3 grid(NROWS / BM, JCHUNKS);
    supcon_hmma<<<grid, 256, SM_TOTAL>>>(zau, ztp);
    pt_kernel<<<64, 256>>>(zau, ztp, fc);
    final_kernel<<<1, 256>>>(out);
}

// round 10
// speedup vs baseline: 2.9111x; 1.3148x over previous
#include <cuda_runtime.h>
#include <cuda_bf16.h>
#include <cstdint>

#define NROWS 8192
#define DIM 128
#define ALPHA 2.0f
#define SHIFT 40.0f
#define BM 128
#define BN 64
#define JCHUNKS 16
#define TILES 8              // j-tiles per chunk: 8192/16/64
#define NTHREADS 512

__device__ float g_pos_part[JCHUNKS][NROWS];
__device__ float g_neg_part[JCHUNKS][NROWS];
__device__ float g_at_diag[NROWS];
__device__ float g_pt_part[64];
__device__ double g_fin[64];

// Precomputed bf16 hi/lo split of both inputs (row-major [row*DIM+col])
__device__ __nv_bfloat16 g_au_hi[NROWS * DIM];
__device__ __nv_bfloat16 g_au_lo[NROWS * DIM];
__device__ __nv_bfloat16 g_tp_hi[NROWS * DIM];
__device__ __nv_bfloat16 g_tp_lo[NROWS * DIM];

// ---------------- smem layout (bytes), bf16 tiles, row stride 136 elems (272B)
#define ASTRIDE 136
#define SM_A0 0
#define SM_A1 34816
#define SM_A2 69632
#define SM_A3 104448
#define SM_B0 139264
#define SM_B1 156672
#define SM_B2 174080
#define SM_B3 191488
#define SM_TOTAL 208896
#define MSTEP (16u * ASTRIDE * 2u)

__device__ __forceinline__ uint32_t smem_u32(const void* p) {
    uint32_t a;
    asm("{ .reg .u64 t; cvta.to.shared.u64 t, %1; cvt.u32.u64 %0, t; }" : "=r"(a) : "l"(p));
    return a;
}

#define LDSM4(r0, r1, r2, r3, addr)                                              \
    asm volatile("ldmatrix.sync.aligned.m8n8.x4.shared.b16 {%0,%1,%2,%3}, [%4];" \
                 : "=r"(r0), "=r"(r1), "=r"(r2), "=r"(r3) : "r"(addr))

#define MMA16816(d, a, b0r, b1r)                                                \
    asm volatile("mma.sync.aligned.m16n8k16.row.col.f32.bf16.bf16.f32 "         \
                 "{%0,%1,%2,%3}, {%4,%5,%6,%7}, {%8,%9}, {%0,%1,%2,%3};"        \
                 : "+f"((d)[0]), "+f"((d)[1]), "+f"((d)[2]), "+f"((d)[3])       \
                 : "r"((a)[0]), "r"((a)[1]), "r"((a)[2]), "r"((a)[3]),          \
                   "r"(b0r), "r"(b1r))

#define CP_ASYNC16(dst, src)                                                    \
    asm volatile("cp.async.cg.shared.global [%0], [%1], 16;"                    \
                 :: "r"(dst), "l"(src) : "memory")
#define CP_COMMIT() asm volatile("cp.async.commit_group;" ::: "memory")
#define CP_WAIT0()  asm volatile("cp.async.wait_group 0;" ::: "memory")

// One-shot bf16 hi/lo split of both matrices.
__global__ void split_kernel(const float* __restrict__ zau, const float* __restrict__ ztp) {
    const int e = blockIdx.x * 256 + threadIdx.x;   // one float4 each, 0..262143
    float4 va = ((const float4*)zau)[e];
    float4 vt = ((const float4*)ztp)[e];
    __nv_bfloat162 ah01 = __floats2bfloat162_rn(va.x, va.y);
    __nv_bfloat162 ah23 = __floats2bfloat162_rn(va.z, va.w);
    float2 af01 = __bfloat1622float2(ah01);
    float2 af23 = __bfloat1622float2(ah23);
    __nv_bfloat162 al01 = __floats2bfloat162_rn(va.x - af01.x, va.y - af01.y);
    __nv_bfloat162 al23 = __floats2bfloat162_rn(va.z - af23.x, va.w - af23.y);
    __nv_bfloat162 th01 = __floats2bfloat162_rn(vt.x, vt.y);
    __nv_bfloat162 th23 = __floats2bfloat162_rn(vt.z, vt.w);
    float2 tf01 = __bfloat1622float2(th01);
    float2 tf23 = __bfloat1622float2(th23);
    __nv_bfloat162 tl01 = __floats2bfloat162_rn(vt.x - tf01.x, vt.y - tf01.y);
    __nv_bfloat162 tl23 = __floats2bfloat162_rn(vt.z - tf23.x, vt.w - tf23.y);
    *(uint2*)&g_au_hi[e * 4] = make_uint2(*(uint32_t*)&ah01, *(uint32_t*)&ah23);
    *(uint2*)&g_au_lo[e * 4] = make_uint2(*(uint32_t*)&al01, *(uint32_t*)&al23);
    *(uint2*)&g_tp_hi[e * 4] = make_uint2(*(uint32_t*)&th01, *(uint32_t*)&th23);
    *(uint2*)&g_tp_lo[e * 4] = make_uint2(*(uint32_t*)&tl01, *(uint32_t*)&tl23);
}

__global__ __launch_bounds__(NTHREADS, 1)
void supcon_hmma(int dummy) {
    extern __shared__ char smem[];
    const uint32_t sb = smem_u32(smem);
    const int tid = threadIdx.x;
    const int wid = tid >> 5, lane = tid & 31;
    const int wm = wid & 3, wn = wid >> 2;          // warp grid 4(M) x 4(N)
    const int m0 = wm * 32, n0 = wn * 16;
    const int g = lane >> 2, t4 = lane & 3;
    const int ibase = blockIdx.x * BM;
    const int jcbase = blockIdx.y * (NROWS / JCHUNKS);

    const __nv_bfloat16* gsrc[4] = {g_au_hi, g_au_lo, g_tp_hi, g_tp_lo};
    const uint32_t smA[4] = {sb + SM_A0, sb + SM_A1, sb + SM_A2, sb + SM_A3};
    const uint32_t smB[4] = {sb + SM_B0, sb + SM_B1, sb + SM_B2, sb + SM_B3};

    // Prologue: cp.async A tiles (resident) + B tile 0.
#pragma unroll
    for (int a = 0; a < 4; ++a) {
        const char* gb = (const char*)(gsrc[a] + (size_t)ibase * DIM);
#pragma unroll
        for (int i = 0; i < 4; ++i) {
            int idx = tid + i * NTHREADS;            // 0..2047
            int row = idx >> 4, c = idx & 15;
            CP_ASYNC16(smA[a] + (uint32_t)(row * ASTRIDE + c * 8) * 2u,
                       __cvta_generic_to_global(gb + ((size_t)row * DIM + c * 8) * 2));
        }
        const char* gbB = (const char*)(gsrc[a] + (size_t)jcbase * DIM);
#pragma unroll
        for (int i = 0; i < 2; ++i) {
            int idx = tid + i * NTHREADS;            // 0..1023
            int row = idx >> 4, c = idx & 15;
            CP_ASYNC16(smB[a] + (uint32_t)(row * ASTRIDE + c * 8) * 2u,
                       __cvta_generic_to_global(gbB + ((size_t)row * DIM + c * 8) * 2));
        }
    }
    CP_COMMIT();

    // ldmatrix per-lane addresses
    const int rowA = (((lane >> 3) & 1) << 3) + (lane & 7);
    const int colA = ((lane >> 4) & 1) << 3;
    const int rowB = (((lane >> 4) & 1) << 3) + (lane & 7);
    const int colB = ((lane >> 3) & 1) << 3;
    uint32_t aAddr[4], bAddr[4];
    {
        const uint32_t aoff = (uint32_t)((m0 + rowA) * ASTRIDE + colA) * 2u;
        const uint32_t boff = (uint32_t)((n0 + rowB) * ASTRIDE + colB) * 2u;
#pragma unroll
        for (int a = 0; a < 4; ++a) { aAddr[a] = smA[a] + aoff; bAddr[a] = smB[a] + boff; }
    }

    const int row_base = ibase + m0 + g;
    float pos_loc[4] = {0.f, 0.f, 0.f, 0.f};
    float neg_loc[4] = {0.f, 0.f, 0.f, 0.f};

    CP_WAIT0();
    __syncthreads();

    for (int t = 0; t < TILES; ++t) {
        const int jb = jcbase + t * BN;

        float acc[3][2][2][4];
#pragma unroll
        for (int mt = 0; mt < 3; ++mt)
#pragma unroll
            for (int m = 0; m < 2; ++m)
#pragma unroll
                for (int n = 0; n < 2; ++n)
#pragma unroll
                    for (int d = 0; d < 4; ++d) acc[mt][m][n][d] = 0.f;

#pragma unroll
        for (int ks = 0; ks < 8; ++ks) {
            const uint32_t koff = ks * 32;           // 16 bf16 = 32B per k-step
            uint32_t bF[4][4];
#pragma unroll
            for (int v = 0; v < 4; ++v)
                LDSM4(bF[v][0], bF[v][1], bF[v][2], bF[v][3], bAddr[v] + koff);

            uint32_t aF[2][4];
            // au_hi: aa(hh), aa(hl), at(hh), at(hl)
            LDSM4(aF[0][0], aF[0][1], aF[0][2], aF[0][3], aAddr[0] + koff);
            LDSM4(aF[1][0], aF[1][1], aF[1][2], aF[1][3], aAddr[0] + MSTEP + koff);
#pragma unroll
            for (int m = 0; m < 2; ++m)
#pragma unroll
                for (int n = 0; n < 2; ++n) {
                    MMA16816(acc[0][m][n], aF[m], bF[0][2 * n], bF[0][2 * n + 1]);
                    MMA16816(acc[0][m][n], aF[m], bF[1][2 * n], bF[1][2 * n + 1]);
                    MMA16816(acc[2][m][n], aF[m], bF[2][2 * n], bF[2][2 * n + 1]);
                    MMA16816(acc[2][m][n], aF[m], bF[3][2 * n], bF[3][2 * n + 1]);
                }
            // au_lo: aa(lh), at(lh)
            LDSM4(aF[0][0], aF[0][1], aF[0][2], aF[0][3], aAddr[1] + koff);
            LDSM4(aF[1][0], aF[1][1], aF[1][2], aF[1][3], aAddr[1] + MSTEP + koff);
#pragma unroll
            for (int m = 0; m < 2; ++m)
#pragma unroll
                for (int n = 0; n < 2; ++n) {
                    MMA16816(acc[0][m][n], aF[m], bF[0][2 * n], bF[0][2 * n + 1]);
                    MMA16816(acc[2][m][n], aF[m], bF[2][2 * n], bF[2][2 * n + 1]);
                }
            // tp_hi: tt(hh), tt(hl)
            LDSM4(aF[0][0], aF[0][1], aF[0][2], aF[0][3], aAddr[2] + koff);
            LDSM4(aF[1][0], aF[1][1], aF[1][2], aF[1][3], aAddr[2] + MSTEP + koff);
#pragma unroll
            for (int m = 0; m < 2; ++m)
#pragma unroll
                for (int n = 0; n < 2; ++n) {
                    MMA16816(acc[1][m][n], aF[m], bF[2][2 * n], bF[2][2 * n + 1]);
                    MMA16816(acc[1][m][n], aF[m], bF[3][2 * n], bF[3][2 * n + 1]);
                }
            // tp_lo: tt(lh)
            LDSM4(aF[0][0], aF[0][1], aF[0][2], aF[0][3], aAddr[3] + koff);
            LDSM4(aF[1][0], aF[1][1], aF[1][2], aF[1][3], aAddr[3] + MSTEP + koff);
#pragma unroll
            for (int m = 0; m < 2; ++m)
#pragma unroll
                for (int n = 0; n < 2; ++n)
                    MMA16816(acc[1][m][n], aF[m], bF[2][2 * n], bF[2][2 * n + 1]);
        }

        __syncthreads();   // all warps done reading B tile t

        // Issue next B tile loads; they run under the exp epilogue below.
        if (t + 1 < TILES) {
            const int jn = jcbase + (t + 1) * BN;
#pragma unroll
            for (int a = 0; a < 4; ++a) {
                const char* gbB = (const char*)(gsrc[a] + (size_t)jn * DIM);
#pragma unroll
                for (int i = 0; i < 2; ++i) {
                    int idx = tid + i * NTHREADS;
                    int row = idx >> 4, c = idx & 15;
                    CP_ASYNC16(smB[a] + (uint32_t)(row * ASTRIDE + c * 8) * 2u,
                               __cvta_generic_to_global(gbB + ((size_t)row * DIM + c * 8) * 2));
                }
            }
            CP_COMMIT();
        }

        // Register-only epilogue: exp-sums with diagonal exclusion.
        const int col_base = jb + n0 + 2 * t4;
#pragma unroll
        for (int m = 0; m < 2; ++m)
#pragma unroll
            for (int n = 0; n < 2; ++n)
#pragma unroll
                for (int d = 0; d < 4; ++d) {
                    const int gi = row_base + m * 16 + ((d >> 1) << 3);
                    const int gj = col_base + n * 8 + (d & 1);
                    float e1 = __expf(acc[0][m][n][d] - SHIFT) +
                               __expf(acc[1][m][n][d] - SHIFT);
                    float e2 = __expf(acc[2][m][n][d] - SHIFT);
                    if (gi != gj) {
                        pos_loc[m * 2 + (d >> 1)] += e1;
                        neg_loc[m * 2 + (d >> 1)] += e2;
                    }
                }

        if (t + 1 < TILES) CP_WAIT0();
        __syncthreads();
    }

    // Reduce across t4 lanes, then across wn warps via smem (reuses A region).
#pragma unroll
    for (int i = 0; i < 4; ++i) {
        pos_loc[i] += __shfl_xor_sync(0xffffffff, pos_loc[i], 1);
        pos_loc[i] += __shfl_xor_sync(0xffffffff, pos_loc[i], 2);
        neg_loc[i] += __shfl_xor_sync(0xffffffff, neg_loc[i], 1);
        neg_loc[i] += __shfl_xor_sync(0xffffffff, neg_loc[i], 2);
    }
    float* rf = (float*)smem;   // [0:512) pos[row][wn], [512:1024) neg[row][wn]
    if (t4 == 0) {
#pragma unroll
        for (int i = 0; i < 4; ++i) {
            const int row = m0 + (i >> 1) * 16 + (i & 1) * 8 + g;
            rf[row * 4 + wn] = pos_loc[i];
            rf[512 + row * 4 + wn] = neg_loc[i];
        }
    }
    __syncthreads();
    if (tid < 128) {
        g_pos_part[blockIdx.y][ibase + tid] =
            rf[tid * 4] + rf[tid * 4 + 1] + rf[tid * 4 + 2] + rf[tid * 4 + 3];
        g_neg_part[blockIdx.y][ibase + tid] =
            rf[512 + tid * 4] + rf[512 + tid * 4 + 1] +
            rf[512 + tid * 4 + 2] + rf[512 + tid * 4 + 3];
    }
}

// Exact fp32 diagonal: g_at_diag[i] = dot(au_i, tp_i)
__global__ void diag_kernel(const float* __restrict__ zau, const float* __restrict__ ztp) {
    const int row = blockIdx.x * 8 + (threadIdx.x >> 5);
    const int lid = threadIdx.x & 31;
    float4 a = *(const float4*)(zau + (size_t)row * DIM + lid * 4);
    float4 b = *(const float4*)(ztp + (size_t)row * DIM + lid * 4);
    float s = a.x * b.x + a.y * b.y + a.z * b.z + a.w * b.w;
#pragma unroll
    for (int off = 16; off > 0; off >>= 1)
        s += __shfl_xor_sync(0xffffffff, s, off);
    if (lid == 0) g_at_diag[row] = s;
}

// pt_loss partials: sum over rows of (au - tp) . (pt1 - pt0)
__global__ void pt_kernel(const float* __restrict__ zau, const float* __restrict__ ztp,
                          const float* __restrict__ fc) {
    __shared__ float w[DIM];
    __shared__ float red[256];
    const int tid = threadIdx.x;
    if (tid < DIM) w[tid] = fc[DIM + tid] - fc[tid];
    __syncthreads();
    float s = 0.f;
    const size_t base = (size_t)blockIdx.x * 16384;
    for (int e = tid; e < 16384; e += 256)
        s += (zau[base + e] - ztp[base + e]) * w[e & (DIM - 1)];
    red[tid] = s;
    __syncthreads();
    for (int off = 128; off > 0; off >>= 1) {
        if (tid < off) red[tid] += red[tid + off];
        __syncthreads();
    }
    if (tid == 0) g_pt_part[blockIdx.x] = red[0];
}

// Stage 1: per-row supcon terms, 64 blocks x 128 rows.
__global__ void final1_kernel() {
    __shared__ double red[128];
    const int tid = threadIdx.x;
    const int i = blockIdx.x * 128 + tid;
    float ps = 0.f, ns = 0.f;
#pragma unroll
    for (int c = 0; c < JCHUNKS; ++c) {
        ps += g_pos_part[c][i];
        ns += g_neg_part[c][i];
    }
    red[tid] = (double)(logf(ns) - logf(ps) + ALPHA * g_at_diag[i]);
    __syncthreads();
    for (int off = 64; off > 0; off >>= 1) {
        if (tid < off) red[tid] += red[tid + off];
        __syncthreads();
    }
    if (tid == 0) g_fin[blockIdx.x] = red[0];
}

// Stage 2: combine.
__global__ void final2_kernel(float* __restrict__ out) {
    __shared__ double red[64];
    const int tid = threadIdx.x;
    red[tid] = g_fin[tid];
    __syncthreads();
    for (int off = 32; off > 0; off >>= 1) {
        if (tid < off) red[tid] += red[tid + off];
        __syncthreads();
    }
    if (tid == 0) {
        double pt = 0.0;
        for (int b = 0; b < 64; ++b) pt += (double)g_pt_part[b];
        pt /= (double)NROWS;
        out[0] = (float)((pt + red[0]) / (double)(NROWS + 2));
    }
}

extern "C" void kernel_launch(void* const* d_in, const int* in_sizes, int n_in,
                              void* d_out, int out_size) {
    const float* zau = (const float*)d_in[0];   // [8192,128] f32
    const float* ztp = (const float*)d_in[1];   // [8192,128] f32
    const float* fc  = (const float*)d_in[2];   // [2,128] f32
    // d_in[3]: labels (int64) — unused by the math.
    float* out = (float*)d_out;

    cudaFuncSetAttribute(supcon_hmma, cudaFuncAttributeMaxDynamicSharedMemorySize, SM_TOTAL);

    split_kernel<<<1024, 256>>>(zau, ztp);
    diag_kernel<<<1024, 256>>>(zau, ztp);
    dim3 grid(NROWS / BM, JCHUNKS);
    supcon_hmma<<<grid, NTHREADS, SM_TOTAL>>>(0);
    pt_kernel<<<64, 256>>>(zau, ztp, fc);
    final1_kernel<<<64, 128>>>();
    final2_kernel<<<1, 64>>>(out);
}